// round 9
// baseline (speedup 1.0000x reference)
#include <cuda_runtime.h>

#define Bsz 2
#define Nn  4096
#define Cc  192
#define Hh  8
#define Dd  24
#define JCH 64                  // j-rows per task (one block per SM, uniform)
#define NBLK 128
#define NT   512

#define FPSCALE 4194304.0f      // 2^22
#define FPINV   (1.0f / 4194304.0f)

// Scratch (__device__ globals; no allocations allowed)
__device__ float g_wksum[Hh * Cc];
__device__ unsigned long long g_Ufp[Bsz * Cc * Hh];   // [b][t'*8 + h]
__device__ unsigned long long g_zfp[Bsz * Hh];
__device__ unsigned int g_ac_done = 0;

// ---------------------------------------------------------------------------
// Prelude: wksum; zero fixed-point accumulators + flag (graph edge orders this).
// ---------------------------------------------------------------------------
__global__ void k_pre(const float* __restrict__ Wqkv) {
    int gid = blockIdx.x * 512 + threadIdx.x;          // 0..1535
    g_Ufp[gid] = 0ull;
    g_Ufp[gid + 1536] = 0ull;
    if (gid < Bsz * Hh) g_zfp[gid] = 0ull;
    if (gid == 0) g_ac_done = 0;
    int h = gid / Cc, c = gid - h * Cc;
    const float* base = Wqkv + (size_t)(Cc + h * Dd) * Cc + c;
    float s = 0.f;
#pragma unroll
    for (int d = 0; d < Dd; d++) s += base[(size_t)d * Cc];
    g_wksum[gid] = s;
}

// ---------------------------------------------------------------------------
__global__ __launch_bounds__(NT, 1)
void fused_kernel(const float* __restrict__ x,
                  const float* __restrict__ Wqkv,
                  const float* __restrict__ Wproj,
                  const float* __restrict__ bproj,
                  const float* __restrict__ scale,
                  float4* __restrict__ out) {
    __shared__ __align__(16) float4 s_ws4[Hh * 49];     // padded: row stride 49 f4
    __shared__ __align__(16) float  s_et[JCH * Hh];     // transposed [j][h]
    __shared__ float  s_zp[Hh * 16];                    // per-(h, warp) z partials
    __shared__ __align__(16) float  s_part[Hh * Cc];    // jg1 xw partial
    __shared__ __align__(16) float  s_comb[Hh * Cc];    // combined xw
    __shared__ __align__(16) float  s_ov[Cc];
    __shared__ float  s_invz[Bsz * Hh];
    __shared__ __align__(16) float  s_y[Bsz * Cc];

    const int tid  = threadIdx.x;
    const int bid  = blockIdx.x;
    const int warp = tid >> 5;                          // 0..15
    const int lane = tid & 31;

    const int b     = bid >> 6;
    const int chunk = bid & 63;
    const int j0    = chunk * JCH;

    // ---- stage wksum into padded f4 layout ----
    if (tid < 384) {
        const int h = tid / 48, q = tid - h * 48;
        s_ws4[h * 49 + q] = ((const float4*)g_wksum)[tid];
    }
    __syncthreads();

    // ---- e phase: thread (j,h) owns a full 192-dot; no reduction shuffles ----
    {
        const float sc = __ldg(scale);
        const int j = tid >> 3;                         // 0..63
        const int h = tid & 7;
        const float4* xr = (const float4*)(x + (size_t)(b * Nn + j0 + j) * Cc);
        const float4* wr = s_ws4 + h * 49;
        float p = 0.f;
#pragma unroll 8
        for (int q = 0; q < 48; q++) {
            float4 a = xr[q], w = wr[q];
            p += a.x * w.x + a.y * w.y + a.z * w.z + a.w * w.w;
        }
        float e = __expf(p * sc);
        s_et[j * Hh + h] = e;
        // z partial over the warp's 4 j-values (same h): 2 shuffles
        float z = e;
        z += __shfl_down_sync(0xffffffffu, z, 16);
        z += __shfl_down_sync(0xffffffffu, z, 8);
        if (lane < 8) s_zp[lane * 16 + warp] = z;       // h == lane here
    }
    __syncthreads();

    // ---- xw partials (threads 0..383, 2 jg x 32 rows) + Z (warps 12..15) ----
    {
        const int jg = tid / Cc;
        const int c  = tid - jg * Cc;
        float acc[Hh];
#pragma unroll
        for (int h = 0; h < Hh; h++) acc[h] = 0.f;

        if (tid < 2 * Cc) {
            const float* xp = x + ((size_t)(b * Nn + j0 + jg * 32)) * Cc + c;
#pragma unroll 4
            for (int q = 0; q < 32; q++) {
                float xv = xp[(size_t)q * Cc];          // L1-hot from e phase
                const int wj = jg * 32 + q;
                float4 e0 = ((const float4*)s_et)[wj * 2];      // h 0..3
                float4 e1 = ((const float4*)s_et)[wj * 2 + 1];  // h 4..7
                acc[0] += e0.x * xv; acc[1] += e0.y * xv;
                acc[2] += e0.z * xv; acc[3] += e0.w * xv;
                acc[4] += e1.x * xv; acc[5] += e1.y * xv;
                acc[6] += e1.z * xv; acc[7] += e1.w * xv;
            }
        } else if (warp >= 12) {                        // Z: 4 warps x 2 heads
            const int h = (warp - 12) * 2 + (lane >> 4);
            const int l = lane & 15;
            float z = s_zp[h * 16 + l];
#pragma unroll
            for (int o = 8; o > 0; o >>= 1) z += __shfl_xor_sync(0xffffffffu, z, o);
            if (l == 0)
                atomicAdd(&g_zfp[b * Hh + h],
                          (unsigned long long)__float2ll_rn(z * FPSCALE));
        }
        __syncthreads();
        if (jg == 1) {
#pragma unroll
            for (int h = 0; h < Hh; h++) s_part[h * Cc + c] = acc[h];
        }
        __syncthreads();
        if (jg == 0) {
#pragma unroll
            for (int h = 0; h < Hh; h++) s_comb[h * Cc + c] = acc[h] + s_part[h * Cc + c];
        }
    }
    __syncthreads();

    // ---- ovu partial: thread t owns full 192-dot (f4), no shuffles ----
    if (tid < Cc) {
        const int t = tid;
        const int h = t / Dd;
        const float4* wv = (const float4*)(Wqkv + (size_t)(2 * Cc + t) * Cc);
        const float4* cb = (const float4*)(s_comb + h * Cc);
        float p = 0.f;
#pragma unroll 8
        for (int q = 0; q < 48; q++) {
            float4 w4 = wv[q], c4 = cb[q];
            p += w4.x * c4.x + w4.y * c4.y + w4.z * c4.z + w4.w * c4.w;
        }
        s_ov[t] = p;
    }
    __syncthreads();

    // ---- U partial: o = t'*8 + h; 3 outputs/thread; fixed-point atomics ----
    {
#pragma unroll
        for (int k = 0; k < 3; k++) {
            const int o  = tid + k * NT;                // 0..1535
            const int tp = o >> 3, h = o & 7;
            const float4* wp = (const float4*)(Wproj + (size_t)tp * Cc + h * Dd);
            const float4* ov = (const float4*)(s_ov + h * Dd);
            float s = 0.f;
#pragma unroll
            for (int q = 0; q < 6; q++) {
                float4 w4 = wp[q], o4 = ov[q];
                s += w4.x * o4.x + w4.y * o4.y + w4.z * o4.z + w4.w * o4.w;
            }
            atomicAdd(&g_Ufp[b * 1536 + o],
                      (unsigned long long)__float2ll_rn(s * FPSCALE));
        }
    }
    __threadfence();
    __syncthreads();
    if (tid == 0) atomicAdd(&g_ac_done, 1u);

    // ---- single arrival-spin sync ----
    if (tid == 0) {
        volatile unsigned int* p = &g_ac_done;
        while (*p < (unsigned)NBLK) __nanosleep(64);
    }
    __syncthreads();
    __threadfence();

    // ---- every block redundantly computes y (pure function of U,Z) ----
    if (tid < Bsz * Hh)
        s_invz[tid] = 1.f / ((float)(long long)g_zfp[tid] * FPINV);
    __syncthreads();
    if (tid < Bsz * Cc) {
        const int b2 = tid / Cc, tp = tid - b2 * Cc;
        const unsigned long long* up = g_Ufp + b2 * 1536 + tp * 8;
        float s = bproj[tp];
#pragma unroll
        for (int h = 0; h < Hh; h++)
            s += s_invz[b2 * Hh + h] * ((float)(long long)up[h] * FPINV);
        s_y[tid] = s;
    }
    __syncthreads();

    // ---- broadcast: 128 * 3072 = 393216 float4 ----
    {
        const float4* sy4 = (const float4*)s_y;
        const int base = bid * 3072;
#pragma unroll
        for (int k = 0; k < 6; k++) {
            int g  = base + k * NT + tid;
            int r  = g % 48;
            int bb = (g >= Nn * 48) ? 1 : 0;
            out[g] = sy4[bb * 48 + r];
        }
    }
}

extern "C" void kernel_launch(void* const* d_in, const int* in_sizes, int n_in,
                              void* d_out, int out_size) {
    const float* x     = (const float*)d_in[0];
    const float* Wqkv  = (const float*)d_in[1];
    const float* Wproj = (const float*)d_in[2];
    const float* bproj = (const float*)d_in[3];
    const float* scale = (const float*)d_in[4];

    k_pre<<<3, 512>>>(Wqkv);
    fused_kernel<<<NBLK, NT>>>(x, Wqkv, Wproj, bproj, scale, (float4*)d_out);
}